// round 17
// baseline (speedup 1.0000x reference)
#include <cuda_runtime.h>
#include <cuda_fp16.h>
#include <cstdint>

#define NN   4096
#define DD   16
#define BB   32
#define CI   32
#define CO   32
#define JTOT (BB*CI)     // 1024
#define KIO  (2*CI*CO)   // 2048

// ---------------- scratch ----------------
__device__ __half g_Ph[(size_t)NN*NN];     // 32MB  fp16 exp(v - rowmax)
__device__ float  g_rinv[NN];
__device__ __half g_Wh[(size_t)NN*KIO];    // 16MB  fp16 weights [n][i'=k*32+i][o]
__device__ float  g_bias[(size_t)NN*CO];   // 512KB
__device__ __half g_Xt[(size_t)JTOT*NN];   // 8MB   Xt[j][m] (GEMM B operand)
__device__ __half g_Xn[(size_t)NN*JTOT];   // 8MB   Xn[m][b*32+c]
__device__ __half g_Ya[(size_t)NN*JTOT];   // 8MB   Ya[n][b*32+c] = fp16(rinv*Y)

// ---------------- helpers ----------------
__device__ __forceinline__ uint32_t smem_u32(const void* p) {
    uint32_t a;
    asm("{ .reg .u64 t; cvta.to.shared.u64 t, %1; cvt.u32.u64 %0, t; }" : "=r"(a) : "l"(p));
    return a;
}
union F2 { float2 f; unsigned long long u; };
__device__ __forceinline__ F2 pack2(float x, float y) {
    F2 r; asm("mov.b64 %0, {%1, %2};" : "=l"(r.u) : "f"(x), "f"(y)); return r;
}
__device__ __forceinline__ void fma2(F2& c, F2 a, F2 b) {
    asm("fma.rn.f32x2 %0, %1, %2, %0;" : "+l"(c.u) : "l"(a.u), "l"(b.u));
}
__device__ __forceinline__ void cp16(uint32_t dst, const void* src) {
    asm volatile("cp.async.cg.shared.global [%0], [%1], 16;" :: "r"(dst), "l"(src));
}
__device__ __forceinline__ void ldm4(uint32_t* r, uint32_t addr) {
    asm volatile("ldmatrix.sync.aligned.m8n8.x4.shared.b16 {%0,%1,%2,%3}, [%4];"
                 : "=r"(r[0]), "=r"(r[1]), "=r"(r[2]), "=r"(r[3]) : "r"(addr));
}
__device__ __forceinline__ void ldm4t(uint32_t* r, uint32_t addr) {
    asm volatile("ldmatrix.sync.aligned.m8n8.x4.trans.shared.b16 {%0,%1,%2,%3}, [%4];"
                 : "=r"(r[0]), "=r"(r[1]), "=r"(r[2]), "=r"(r[3]) : "r"(addr));
}
__device__ __forceinline__ void mma_f16(float* c, const uint32_t* a, const uint32_t* b) {
    asm volatile(
        "mma.sync.aligned.m16n8k16.row.col.f32.f16.f16.f32 "
        "{%0,%1,%2,%3}, {%4,%5,%6,%7}, {%8,%9}, {%0,%1,%2,%3};"
        : "+f"(c[0]), "+f"(c[1]), "+f"(c[2]), "+f"(c[3])
        : "r"(a[0]), "r"(a[1]), "r"(a[2]), "r"(a[3]), "r"(b[0]), "r"(b[1]));
}
#define SWZ128(off) ((off) ^ (((off) >> 3) & 0x70))

// ---- kernel 1: 8 rows/block, 128KB smem logits -> Ph, rinv, bias ----
#define SROWS 8
__global__ void __launch_bounds__(256) k_supports(const float* __restrict__ E,
                                                  const float* __restrict__ bp) {
    extern __shared__ float sL[];
    __shared__ float es[SROWS*DD];
    __shared__ float red[SROWS][8];
    __shared__ float rowred[SROWS];
    const int tid = threadIdx.x;
    const int n0  = blockIdx.x * SROWS;

    if (tid < SROWS*DD) es[tid] = E[n0*DD + tid];
    __syncthreads();
    F2 ereg2[SROWS][DD/2];
    #pragma unroll
    for (int r = 0; r < SROWS; r++)
        #pragma unroll
        for (int dd = 0; dd < DD/2; dd++)
            ereg2[r][dd] = pack2(es[r*DD + 2*dd], es[r*DD + 2*dd + 1]);

    float mx[SROWS];
    #pragma unroll
    for (int r = 0; r < SROWS; r++) mx[r] = 0.f;
    for (int m = tid; m < NN; m += 256) {
        const float4* e4 = reinterpret_cast<const float4*>(E + (size_t)m*DD);
        float4 u0 = e4[0], u1 = e4[1], u2 = e4[2], u3 = e4[3];
        F2 av[8];
        av[0] = pack2(u0.x, u0.y); av[1] = pack2(u0.z, u0.w);
        av[2] = pack2(u1.x, u1.y); av[3] = pack2(u1.z, u1.w);
        av[4] = pack2(u2.x, u2.y); av[5] = pack2(u2.z, u2.w);
        av[6] = pack2(u3.x, u3.y); av[7] = pack2(u3.z, u3.w);
        #pragma unroll
        for (int r = 0; r < SROWS; r++) {
            F2 acc; acc.u = 0ull;
            #pragma unroll
            for (int dd = 0; dd < DD/2; dd++) fma2(acc, av[dd], ereg2[r][dd]);
            float d = fmaxf(acc.f.x + acc.f.y, 0.f);
            sL[r*NN + m] = d;
            mx[r] = fmaxf(mx[r], d);
        }
    }
    #pragma unroll
    for (int r = 0; r < SROWS; r++) {
        float s = mx[r];
        #pragma unroll
        for (int o = 16; o > 0; o >>= 1) s = fmaxf(s, __shfl_xor_sync(0xffffffffu, s, o));
        if ((tid & 31) == 0) red[r][tid >> 5] = s;
    }
    __syncthreads();
    if (tid < SROWS) {
        float t = red[tid][0];
        #pragma unroll
        for (int w = 1; w < 8; w++) t = fmaxf(t, red[tid][w]);
        rowred[tid] = t;
    }
    __syncthreads();
    float rm[SROWS];
    #pragma unroll
    for (int r = 0; r < SROWS; r++) rm[r] = rowred[r];

    float sum[SROWS];
    #pragma unroll
    for (int r = 0; r < SROWS; r++) sum[r] = 0.f;
    for (int m2 = tid; m2 < NN/2; m2 += 256) {
        #pragma unroll
        for (int r = 0; r < SROWS; r++) {
            float2 d = *reinterpret_cast<const float2*>(&sL[r*NN + 2*m2]);
            float p0 = __expf(d.x - rm[r]);
            float p1 = __expf(d.y - rm[r]);
            __half2 h = __floats2half2_rn(p0, p1);
            *reinterpret_cast<__half2*>(&g_Ph[(size_t)(n0 + r)*NN + 2*m2]) = h;
            sum[r] += __half2float(__low2half(h)) + __half2float(__high2half(h));
        }
    }
    #pragma unroll
    for (int r = 0; r < SROWS; r++) {
        float s = sum[r];
        #pragma unroll
        for (int o = 16; o > 0; o >>= 1) s += __shfl_xor_sync(0xffffffffu, s, o);
        if ((tid & 31) == 0) red[r][tid >> 5] = s;
    }
    __syncthreads();
    if (tid < SROWS) {
        float t = 0.f;
        #pragma unroll
        for (int w = 0; w < 8; w++) t += red[tid][w];
        g_rinv[n0 + tid] = 1.0f / t;
    }
    {
        int r = tid >> 5, o = tid & 31;
        float acc = 0.f;
        #pragma unroll
        for (int d = 0; d < DD; d++) acc = fmaf(es[r*DD + d], bp[d*CO + o], acc);
        g_bias[(n0 + r)*CO + o] = acc;
    }
}

// ---- kernel 1b: Xt[j][m] and Xn[m][j] = fp16(x[b,m,c]) ----
__global__ void __launch_bounds__(256) k_tr(const float* __restrict__ x) {
    __shared__ float s[32*33];
    const int tid = threadIdx.x;
    const int b   = blockIdx.y;
    const int m0  = blockIdx.x * 32;
    #pragma unroll
    for (int q = 0; q < 4; q++) {
        int idx = tid + q*256;
        int m = idx >> 5, c = idx & 31;
        s[c*33 + m] = x[(size_t)b*NN*CI + (size_t)(m0 + m)*CI + c];
    }
    __syncthreads();
    #pragma unroll
    for (int q = 0; q < 2; q++) {
        int idx2 = tid + q*256;
        {
            int jl = idx2 >> 4, mo2 = idx2 & 15;
            __half2 h = __floats2half2_rn(s[jl*33 + 2*mo2], s[jl*33 + 2*mo2 + 1]);
            *reinterpret_cast<__half2*>(&g_Xt[(size_t)(b*32 + jl)*NN + m0 + 2*mo2]) = h;
        }
        {
            int m = idx2 >> 4, c2 = idx2 & 15;
            __half2 h = __floats2half2_rn(s[(2*c2)*33 + m], s[(2*c2+1)*33 + m]);
            *reinterpret_cast<__half2*>(&g_Xn[(size_t)(m0 + m)*JTOT + b*32 + 2*c2]) = h;
        }
    }
}

// ------ kernel 2: Wh[n][kio] = fp16(sum_d E[n][d] * wp[d][kio]), f32x2 ------
__global__ void __launch_bounds__(256) k_wgen(const float* __restrict__ E,
                                              const float* __restrict__ wp) {
    const int col2 = blockIdx.x * 256 + threadIdx.x;
    const int n0   = blockIdx.y * 128;
    __shared__ float es[128 * DD];
    for (int t = threadIdx.x; t < 128*DD; t += 256) es[t] = E[n0*DD + t];
    F2 wx[DD/2], wy[DD/2];
    #pragma unroll
    for (int dd = 0; dd < DD/2; dd++) {
        float2 wa = *reinterpret_cast<const float2*>(&wp[(2*dd)*KIO + 2*col2]);
        float2 wb = *reinterpret_cast<const float2*>(&wp[(2*dd+1)*KIO + 2*col2]);
        wx[dd] = pack2(wa.x, wb.x);
        wy[dd] = pack2(wa.y, wb.y);
    }
    __syncthreads();
    #pragma unroll 4
    for (int n = 0; n < 128; n++) {
        F2 accx, accy; accx.u = accy.u = 0ull;
        #pragma unroll
        for (int dd = 0; dd < DD/2; dd++) {
            F2 ep; ep.f = *reinterpret_cast<const float2*>(&es[n*DD + 2*dd]);
            fma2(accx, ep, wx[dd]);
            fma2(accy, ep, wy[dd]);
        }
        *reinterpret_cast<__half2*>(&g_Wh[(size_t)(n0 + n)*KIO + 2*col2]) =
            __floats2half2_rn(accx.f.x + accx.f.y, accy.f.x + accy.f.y);
    }
}

// ---- kernel 3: GEMM mainloop -> g_Ya (fp16, rinv folded) ------------------
#define NITER   (NN/64)          // 64
#define STAGEB  49152
#define SM_DATA 1024
#define GSMEM   (SM_DATA + 4*STAGEB)   // 197632
#define YA_OFF  0

__device__ __forceinline__ void issue_loads(uint32_t sbase, int stage, int n0, int col0,
                                            int k0, int tid) {
    const uint32_t sa = sbase + SM_DATA + stage*STAGEB;
    const uint32_t sb = sa + 16384;
    #pragma unroll
    for (int q = 0; q < 4; q++) {
        int gid = tid + q*256;
        int row = gid >> 3, g = gid & 7;
        uint32_t off = row*128 + g*16;
        cp16(sa + SWZ128(off), g_Ph + (size_t)(n0 + row)*NN + k0 + g*8);
    }
    #pragma unroll
    for (int q = 0; q < 8; q++) {
        int gid = tid + q*256;
        int row = gid >> 3, g = gid & 7;
        uint32_t off = row*128 + g*16;
        cp16(sb + SWZ128(off), g_Xt + (size_t)(col0 + row)*NN + k0 + g*8);
    }
    asm volatile("cp.async.commit_group;" ::: "memory");
}

__global__ void __launch_bounds__(256, 1) k_gemm() {
    extern __shared__ __align__(1024) uint8_t dsm[];
    const uint32_t sbase = smem_u32(dsm);
    const int tid  = threadIdx.x;
    const int wid  = tid >> 5;
    const int lane = tid & 31;
    const int col0 = blockIdx.x * 256;
    const int n0   = blockIdx.y * 128;
    const int b0   = col0 >> 5;

    const int wm = (wid >> 2) * 64;
    const int wn = (wid & 3) * 64;
    const int r   = lane >> 2;
    const int kg  = lane & 3;

    uint32_t aBase[4], aXor[4];
    {
        int rl = (lane & 7) + ((lane >> 3) & 1) * 8;
        #pragma unroll
        for (int t = 0; t < 4; t++) {
            int row = wm + t*16 + rl;
            aBase[t] = (uint32_t)(row * 128);
            aXor[t]  = (uint32_t)((row & 7) << 4);
        }
    }
    const uint32_t aKc = (uint32_t)(((lane >> 4) & 1) * 16);
    uint32_t bBase[4], bXor[4];
    {
        int jl = ((lane >> 4) & 1) * 8 + (lane & 7);
        #pragma unroll
        for (int p = 0; p < 4; p++) {
            int jr = wn + p*16 + jl;
            bBase[p] = 16384u + (uint32_t)(jr * 128);
            bXor[p]  = (uint32_t)((jr & 7) << 4);
        }
    }
    const uint32_t bKc = (uint32_t)(((lane >> 3) & 1) * 16);

    float acc[4][8][4];
    #pragma unroll
    for (int t = 0; t < 4; t++)
        #pragma unroll
        for (int nt = 0; nt < 8; nt++)
            #pragma unroll
            for (int e = 0; e < 4; e++) acc[t][nt][e] = 0.f;

    issue_loads(sbase, 0, n0, col0, 0,   tid);
    issue_loads(sbase, 1, n0, col0, 64,  tid);
    issue_loads(sbase, 2, n0, col0, 128, tid);

    for (int i = 0; i < NITER; i++) {
        asm volatile("cp.async.wait_group 2;" ::: "memory");
        __syncthreads();
        if (i + 3 < NITER) issue_loads(sbase, (i + 3) & 3, n0, col0, (i + 3)*64, tid);

        const uint32_t cur = sbase + SM_DATA + (i & 3)*STAGEB;
        #pragma unroll
        for (int ks = 0; ks < 4; ks++) {
            const uint32_t ka = (uint32_t)(ks*32) + aKc;
            const uint32_t kb = (uint32_t)(ks*32) + bKc;
            uint32_t a[4][4];
            #pragma unroll
            for (int t = 0; t < 4; t++)
                ldm4(a[t], cur + aBase[t] + (ka ^ aXor[t]));
            uint32_t b[8][2];
            #pragma unroll
            for (int p = 0; p < 4; p++) {
                uint32_t rr[4];
                ldm4(rr, cur + bBase[p] + (kb ^ bXor[p]));
                b[2*p][0]   = rr[0]; b[2*p][1]   = rr[1];
                b[2*p+1][0] = rr[2]; b[2*p+1][1] = rr[3];
            }
            #pragma unroll
            for (int t = 0; t < 4; t++)
                #pragma unroll
                for (int nt = 0; nt < 8; nt++)
                    mma_f16(acc[t][nt], a[t], b[nt]);
        }
    }
    asm volatile("cp.async.wait_group 0;" ::: "memory");
    __syncthreads();

    __half* ya_ptr = reinterpret_cast<__half*>(dsm + YA_OFF);
    #pragma unroll
    for (int t = 0; t < 4; t++) {
        const int row0 = wm + t*16 + r;
        const float rv0 = g_rinv[n0 + row0];
        const float rv1 = g_rinv[n0 + row0 + 8];
        #pragma unroll
        for (int nt = 0; nt < 8; nt++) {
            const int col = wn + nt*8 + kg*2;
            const int b = col >> 5, cc = col & 31;
            *reinterpret_cast<__half2*>(&ya_ptr[row0*320 + b*40 + cc]) =
                __floats2half2_rn(acc[t][nt][0]*rv0, acc[t][nt][1]*rv0);
            *reinterpret_cast<__half2*>(&ya_ptr[(row0+8)*320 + b*40 + cc]) =
                __floats2half2_rn(acc[t][nt][2]*rv1, acc[t][nt][3]*rv1);
        }
    }
    __syncthreads();
    #pragma unroll
    for (int q = 0; q < 16; q++) {
        int flat = tid + q*256;
        int rowi = flat >> 5, b = (flat >> 2) & 7, seg = flat & 3;
        float4 v = *reinterpret_cast<const float4*>(
            reinterpret_cast<const uint8_t*>(ya_ptr) + rowi*640 + b*80 + seg*16);
        *reinterpret_cast<float4*>(&g_Ya[(size_t)(n0 + rowi)*JTOT + (b0 + b)*32 + seg*8]) = v;
    }
}

// ---- kernel 4: mma output epilogue, 8 nodes/CTA, 2 CTA/SM -----------------
#define OANODE  4608
#define OW_OFF  36864
#define OWNODE  5120
#define OSMEM   77824

__global__ void __launch_bounds__(256, 2) k_out2(float* __restrict__ out) {
    extern __shared__ __align__(1024) uint8_t dsm[];
    const uint32_t sbase = smem_u32(dsm);
    const int tid  = threadIdx.x;
    const int wid  = tid >> 5;
    const int lane = tid & 31;
    const int n0   = blockIdx.x * 8;

    #pragma unroll
    for (int q = 0; q < 8; q++) {
        int idx = tid + q*256;
        int ns = idx >> 8, rem = idx & 255;
        int b = rem >> 3, s = rem & 7;
        uint32_t dst = sbase + (uint32_t)(ns*OANODE + b*144 + s*16);
        const __half* src = (s < 4)
            ? g_Xn + (size_t)(n0 + ns)*JTOT + b*32 + s*8
            : g_Ya + (size_t)(n0 + ns)*JTOT + b*32 + (s - 4)*8;
        cp16(dst, src);
    }
    #pragma unroll
    for (int q = 0; q < 8; q++) {
        int idx = tid + q*256;
        int ns = idx >> 8, rowi = (idx >> 2) & 63, seg = idx & 3;
        cp16(sbase + OW_OFF + (uint32_t)(ns*OWNODE + rowi*80 + seg*16),
             g_Wh + (size_t)(n0 + ns)*KIO + rowi*32 + seg*8);
    }
    asm volatile("cp.async.commit_group;" ::: "memory");
    asm volatile("cp.async.wait_group 0;" ::: "memory");
    __syncthreads();

    const int n  = n0 + wid;
    const uint32_t ab = sbase + (uint32_t)(wid*OANODE);
    const uint32_t wb = sbase + OW_OFF + (uint32_t)(wid*OWNODE);
    const int arow = lane & 15;
    const uint32_t ahi  = (uint32_t)(((lane >> 4) & 1) * 16);
    const int bmat  = lane >> 3;
    const int bmrow = (lane & 7) + (bmat & 1)*8;

    float C[2][4][4];
    #pragma unroll
    for (int t = 0; t < 2; t++)
        #pragma unroll
        for (int nt = 0; nt < 4; nt++)
            #pragma unroll
            for (int e = 0; e < 4; e++) C[t][nt][e] = 0.f;

    #pragma unroll
    for (int ks = 0; ks < 4; ks++) {
        uint32_t a[2][4];
        #pragma unroll
        for (int t = 0; t < 2; t++)
            ldm4(a[t], ab + (uint32_t)((t*16 + arow)*144 + ks*32) + ahi);
        const uint32_t bb = wb + (uint32_t)((ks*16 + bmrow)*80 + (bmat >> 1)*16);
        uint32_t r1[4], r2[4];
        ldm4t(r1, bb);
        ldm4t(r2, bb + 32);
        uint32_t bfr[2];
        #pragma unroll
        for (int t = 0; t < 2; t++) {
            bfr[0] = r1[0]; bfr[1] = r1[1]; mma_f16(C[t][0], a[t], bfr);
            bfr[0] = r1[2]; bfr[1] = r1[3]; mma_f16(C[t][1], a[t], bfr);
            bfr[0] = r2[0]; bfr[1] = r2[1]; mma_f16(C[t][2], a[t], bfr);
            bfr[0] = r2[2]; bfr[1] = r2[3]; mma_f16(C[t][3], a[t], bfr);
        }
    }

    const int rb = lane >> 2;
    const int oo = (lane & 3) * 2;
    #pragma unroll
    for (int t = 0; t < 2; t++) {
        #pragma unroll
        for (int nt = 0; nt < 4; nt++) {
            const int o = nt*8 + oo;
            float2 bias2 = *reinterpret_cast<const float2*>(&g_bias[n*CO + o]);
            const int b_lo = t*16 + rb;
            *reinterpret_cast<float2*>(&out[(size_t)b_lo*NN*CO + (size_t)n*CO + o]) =
                make_float2(C[t][nt][0] + bias2.x, C[t][nt][1] + bias2.y);
            *reinterpret_cast<float2*>(&out[(size_t)(b_lo+8)*NN*CO + (size_t)n*CO + o]) =
                make_float2(C[t][nt][2] + bias2.x, C[t][nt][3] + bias2.y);
        }
    }
}

// ---------------- launcher: fork/join DAG ----------------------------------
extern "C" void kernel_launch(void* const* d_in, const int* in_sizes, int n_in,
                              void* d_out, int out_size) {
    const float* x  = (const float*)d_in[0];
    const float* wp = (const float*)d_in[1];
    const float* bp = (const float*)d_in[2];
    const float* E  = (const float*)d_in[3];
    float* out = (float*)d_out;

    static bool init_done = false;
    static cudaStream_t s1, s2;
    static cudaEvent_t eRoot, eTr, eW;
    if (!init_done) {
        cudaFuncSetAttribute(k_gemm,     cudaFuncAttributeMaxDynamicSharedMemorySize, GSMEM);
        cudaFuncSetAttribute(k_supports, cudaFuncAttributeMaxDynamicSharedMemorySize, 131072);
        cudaFuncSetAttribute(k_out2,     cudaFuncAttributeMaxDynamicSharedMemorySize, OSMEM);
        cudaStreamCreateWithFlags(&s1, cudaStreamNonBlocking);
        cudaStreamCreateWithFlags(&s2, cudaStreamNonBlocking);
        cudaEventCreateWithFlags(&eRoot, cudaEventDisableTiming);
        cudaEventCreateWithFlags(&eTr,   cudaEventDisableTiming);
        cudaEventCreateWithFlags(&eW,    cudaEventDisableTiming);
        init_done = true;
    }

    // fork
    cudaEventRecord(eRoot, 0);
    cudaStreamWaitEvent(s1, eRoot, 0);
    cudaStreamWaitEvent(s2, eRoot, 0);

    // side stream 1: transpose (needed by gemm + out2)
    dim3 gt(NN/32, BB);
    k_tr<<<gt, 256, 0, s1>>>(x);
    cudaEventRecord(eTr, s1);

    // side stream 2: weight generation (needed only by out2; overlaps gemm)
    dim3 gw(KIO/512, NN/128);
    k_wgen<<<gw, 256, 0, s2>>>(E, wp);
    cudaEventRecord(eW, s2);

    // main stream: supports -> gemm -> out2
    k_supports<<<NN/SROWS, 256, 131072>>>(E, bp);
    cudaStreamWaitEvent(0, eTr, 0);
    dim3 gg(JTOT/256, NN/128);            // (4, 32) = 128 CTAs
    k_gemm<<<gg, 256, GSMEM>>>();
    cudaStreamWaitEvent(0, eW, 0);
    k_out2<<<NN/8, 256, OSMEM>>>(out);
}